// round 11
// baseline (speedup 1.0000x reference)
#include <cuda_runtime.h>
#include <math.h>

#define D 128
#define NGRAPH 128
#define MAXN 100000
#define MAXE 1600000
#define SF_THREADS 1024

// Scratch (static __device__ arrays per allocation rules)
__device__ float g_t0[(size_t)MAXN * D];
__device__ float g_t1[(size_t)MAXN * D];
__device__ float g_gate[MAXN];
__device__ int   g_rowptr[MAXN];
__device__ int   g_cursor[MAXN];     // deg during count; row-end after fill
__device__ int2  g_edges[MAXE];      // (src, __float_as_int(ew)) CSR by dst

// Packed f32x2 helpers (Blackwell sm_100+)
#define FFMA2(acc, a, b) \
    asm("fma.rn.f32x2 %0, %1, %2, %0;" : "+l"(acc) : "l"(a), "l"(b))
#define PACK_DUP(out, x) \
    asm("mov.b64 %0, {%1, %1};" : "=l"(out) : "r"(x))
#define UNPACK2(lo, hi, in) \
    asm("mov.b64 {%0, %1}, %2;" : "=f"(lo), "=f"(hi) : "l"(in))

// ---------------------------------------------------------------------------
// GEMM: out[M,128] = f_in(A) @ W, with optional fused epilogues.
//   in_mode : 0 = A as-is; 1 = relu(A + ib); 2 = A + ib (NO relu)
//   out_mode: 0 = store acc; 1 = store relu(acc + ob);
//             2 = gate: g[r] = sum_j relu(acc_j+ob_j)*gw2_j + gb2
// ---------------------------------------------------------------------------
#define ROWS_PER_WARP 8
#define GEMM_WARPS 8
#define ROWS_PER_BLK (ROWS_PER_WARP * GEMM_WARPS)   // 64

__global__ __launch_bounds__(256) void gemm128_kernel(
    const float* __restrict__ A, const float* __restrict__ W,
    const float* __restrict__ ib, const float* __restrict__ ob,
    const float* __restrict__ gw2, const float* __restrict__ gb2,
    float* __restrict__ out, float* __restrict__ gate,
    int M, int in_mode, int out_mode)
{
    extern __shared__ float sh[];
    float* Wsh  = sh;                  // D*D floats (64KB)
    float* rows = sh + D * D;          // ROWS_PER_BLK * D floats (32KB)

    for (int i = threadIdx.x; i < D * D; i += blockDim.x) Wsh[i] = W[i];

    const int warp = threadIdx.x >> 5;
    const int lane = threadIdx.x & 31;
    const int col  = lane << 2;

    float ob0 = 0.f, ob1 = 0.f, ob2v = 0.f, ob3 = 0.f;
    float w20 = 0.f, w21 = 0.f, w22 = 0.f, w23 = 0.f, gb2v = 0.f;
    if (out_mode) {
        ob0 = ob[col]; ob1 = ob[col + 1]; ob2v = ob[col + 2]; ob3 = ob[col + 3];
    }
    if (out_mode == 2) {
        w20 = gw2[col]; w21 = gw2[col + 1]; w22 = gw2[col + 2]; w23 = gw2[col + 3];
        gb2v = gb2[0];
    }
    __syncthreads();

    const int ngroups = (M + ROWS_PER_BLK - 1) / ROWS_PER_BLK;
    for (int grp = blockIdx.x; grp < ngroups; grp += gridDim.x) {
        const int r0 = grp * ROWS_PER_BLK;

        {
            const int nf4 = ROWS_PER_BLK * (D / 4);
            for (int i = threadIdx.x; i < nf4; i += blockDim.x) {
                const int rr = i >> 5;
                const int cc = (i & 31) << 2;
                const int r  = r0 + rr;
                float4 v = make_float4(0.f, 0.f, 0.f, 0.f);
                if (r < M) v = *(const float4*)&A[(size_t)r * D + cc];
                if (in_mode) {
                    v.x += ib[cc];     v.y += ib[cc + 1];
                    v.z += ib[cc + 2]; v.w += ib[cc + 3];
                    if (in_mode == 1) {
                        v.x = fmaxf(v.x, 0.f); v.y = fmaxf(v.y, 0.f);
                        v.z = fmaxf(v.z, 0.f); v.w = fmaxf(v.w, 0.f);
                    }
                }
                *(float4*)&rows[rr * D + cc] = v;
            }
        }
        __syncthreads();

        // Packed accumulators: [row][pair]
        unsigned long long acc[ROWS_PER_WARP][2];
        #pragma unroll
        for (int r = 0; r < ROWS_PER_WARP; r++) { acc[r][0] = 0ull; acc[r][1] = 0ull; }

        const float* rb = &rows[warp * ROWS_PER_WARP * D];
        #pragma unroll 2
        for (int k = 0; k < D; k += 2) {
            const ulonglong2 wA = *(const ulonglong2*)&Wsh[k * D + col];
            const ulonglong2 wB = *(const ulonglong2*)&Wsh[(k + 1) * D + col];
            #pragma unroll
            for (int r = 0; r < ROWS_PER_WARP; r++) {
                const float2 a2 = *(const float2*)&rb[r * D + k];
                unsigned long long a0, a1;
                PACK_DUP(a0, __float_as_uint(a2.x));
                PACK_DUP(a1, __float_as_uint(a2.y));
                FFMA2(acc[r][0], a0, wA.x);
                FFMA2(acc[r][1], a0, wA.y);
                FFMA2(acc[r][0], a1, wB.x);
                FFMA2(acc[r][1], a1, wB.y);
            }
        }

        if (out_mode == 0) {
            #pragma unroll
            for (int r = 0; r < ROWS_PER_WARP; r++) {
                const int row = r0 + warp * ROWS_PER_WARP + r;
                if (row < M) {
                    float4 o;
                    UNPACK2(o.x, o.y, acc[r][0]);
                    UNPACK2(o.z, o.w, acc[r][1]);
                    *(float4*)&out[(size_t)row * D + col] = o;
                }
            }
        } else if (out_mode == 1) {
            #pragma unroll
            for (int r = 0; r < ROWS_PER_WARP; r++) {
                const int row = r0 + warp * ROWS_PER_WARP + r;
                if (row < M) {
                    float a0, a1, a2v, a3;
                    UNPACK2(a0, a1, acc[r][0]);
                    UNPACK2(a2v, a3, acc[r][1]);
                    *(float4*)&out[(size_t)row * D + col] =
                        make_float4(fmaxf(a0 + ob0, 0.f), fmaxf(a1 + ob1, 0.f),
                                    fmaxf(a2v + ob2v, 0.f), fmaxf(a3 + ob3, 0.f));
                }
            }
        } else {
            #pragma unroll
            for (int r = 0; r < ROWS_PER_WARP; r++) {
                const int row = r0 + warp * ROWS_PER_WARP + r;
                float a0, a1, a2v, a3;
                UNPACK2(a0, a1, acc[r][0]);
                UNPACK2(a2v, a3, acc[r][1]);
                float v = fmaxf(a0 + ob0, 0.f) * w20
                        + fmaxf(a1 + ob1, 0.f) * w21
                        + fmaxf(a2v + ob2v, 0.f) * w22
                        + fmaxf(a3 + ob3, 0.f) * w23;
                #pragma unroll
                for (int o = 16; o; o >>= 1) v += __shfl_xor_sync(0xffffffffu, v, o);
                if (lane == 0 && row < M) gate[row] = v + gb2v;
            }
        }
        __syncthreads();
    }
}

// ---------------------------------------------------------------------------
// CSR build: degree count -> fused single-block scan -> bucket fill
// ---------------------------------------------------------------------------
__global__ __launch_bounds__(256) void deg_kernel(
    const int* __restrict__ dst, int* __restrict__ deg, int NE)
{
    for (int e = blockIdx.x * 256 + threadIdx.x; e < NE; e += gridDim.x * 256)
        atomicAdd(&deg[dst[e]], 1);
}

// Single-block exclusive scan: deg (aliased w/ cursor) -> rowptr, cursor=rowptr
__global__ __launch_bounds__(SF_THREADS) void scan_fused_kernel(
    const int* __restrict__ deg, int* __restrict__ rowptr,
    int* __restrict__ cursor, int n)
{
    __shared__ int ssum[SF_THREADS];
    const int t = threadIdx.x;
    const int C = (n + SF_THREADS - 1) / SF_THREADS;
    const int lo = t * C;
    const int hi = (lo + C < n) ? lo + C : n;

    int s = 0;
    for (int i = lo; i < hi; i++) s += deg[i];
    ssum[t] = s;
    __syncthreads();
    for (int o = 1; o < SF_THREADS; o <<= 1) {
        const int add = (t >= o) ? ssum[t - o] : 0;
        __syncthreads();
        ssum[t] += add;
        __syncthreads();
    }
    int run = ssum[t] - s;   // exclusive base for this chunk
    for (int i = lo; i < hi; i++) {
        const int d = deg[i];   // read BEFORE overwriting (deg aliases cursor)
        rowptr[i] = run;
        cursor[i] = run;
        run += d;
    }
}

__global__ __launch_bounds__(256) void fill_kernel(
    const int* __restrict__ src, const int* __restrict__ dst,
    const float* __restrict__ ew, int* __restrict__ cursor,
    int2* __restrict__ edges, int NE)
{
    for (int e = blockIdx.x * 256 + threadIdx.x; e < NE; e += gridDim.x * 256) {
        const int p = atomicAdd(&cursor[dst[e]], 1);
        edges[p] = make_int2(src[e], __float_as_int(ew[e]));
    }
}

// ---------------------------------------------------------------------------
// CSR gather-aggregate: out[n,:] = sum_{e in csr[n]} ew_e * A[src_e, :]
// One warp per node; lane owns one float4 slice. Edge loop unrolled x4 (MLP=4).
// ---------------------------------------------------------------------------
__global__ __launch_bounds__(256) void gather_kernel(
    const float* __restrict__ A, const int* __restrict__ rowptr,
    const int* __restrict__ rowend, const int2* __restrict__ edges,
    float* __restrict__ out, int M)
{
    const int node = ((blockIdx.x * 256 + threadIdx.x) >> 5);
    if (node >= M) return;
    const int lane = threadIdx.x & 31;
    const int col  = lane << 2;

    const int start = rowptr[node];
    const int end   = rowend[node];

    float4 acc0 = make_float4(0.f, 0.f, 0.f, 0.f);
    float4 acc1 = make_float4(0.f, 0.f, 0.f, 0.f);

    int j = start;
    for (; j + 4 <= end; j += 4) {
        const int2 e0 = edges[j];
        const int2 e1 = edges[j + 1];
        const int2 e2 = edges[j + 2];
        const int2 e3 = edges[j + 3];
        const float4 v0 = *(const float4*)&A[(size_t)e0.x * D + col];
        const float4 v1 = *(const float4*)&A[(size_t)e1.x * D + col];
        const float4 v2 = *(const float4*)&A[(size_t)e2.x * D + col];
        const float4 v3 = *(const float4*)&A[(size_t)e3.x * D + col];
        const float w0 = __int_as_float(e0.y);
        const float w1 = __int_as_float(e1.y);
        const float w2 = __int_as_float(e2.y);
        const float w3 = __int_as_float(e3.y);
        acc0.x = fmaf(w0, v0.x, acc0.x); acc0.y = fmaf(w0, v0.y, acc0.y);
        acc0.z = fmaf(w0, v0.z, acc0.z); acc0.w = fmaf(w0, v0.w, acc0.w);
        acc1.x = fmaf(w1, v1.x, acc1.x); acc1.y = fmaf(w1, v1.y, acc1.y);
        acc1.z = fmaf(w1, v1.z, acc1.z); acc1.w = fmaf(w1, v1.w, acc1.w);
        acc0.x = fmaf(w2, v2.x, acc0.x); acc0.y = fmaf(w2, v2.y, acc0.y);
        acc0.z = fmaf(w2, v2.z, acc0.z); acc0.w = fmaf(w2, v2.w, acc0.w);
        acc1.x = fmaf(w3, v3.x, acc1.x); acc1.y = fmaf(w3, v3.y, acc1.y);
        acc1.z = fmaf(w3, v3.z, acc1.z); acc1.w = fmaf(w3, v3.w, acc1.w);
    }
    for (; j < end; j++) {
        const int2 e = edges[j];
        const float w = __int_as_float(e.y);
        const float4 v = *(const float4*)&A[(size_t)e.x * D + col];
        acc0.x = fmaf(w, v.x, acc0.x); acc0.y = fmaf(w, v.y, acc0.y);
        acc0.z = fmaf(w, v.z, acc0.z); acc0.w = fmaf(w, v.w, acc0.w);
    }

    acc0.x += acc1.x; acc0.y += acc1.y; acc0.z += acc1.z; acc0.w += acc1.w;
    *(float4*)&out[(size_t)node * D + col] = acc0;
}

// ---------------------------------------------------------------------------
// Per-graph softmax attention pool + final MLP, one block per graph.
// ---------------------------------------------------------------------------
#define EBUF_CAP 4096
__global__ __launch_bounds__(128) void attn_kernel(
    const float* __restrict__ T1, const float* __restrict__ b2,
    const float* __restrict__ gate, const int* __restrict__ batch,
    const float* __restrict__ l1W, const float* __restrict__ l1b,
    const float* __restrict__ l2W, const float* __restrict__ l2b,
    float* __restrict__ out, int M)
{
    __shared__ float ebuf[EBUF_CAP];
    __shared__ float sacc[D];
    __shared__ float red[4];
    __shared__ int bounds[2];

    const int b    = blockIdx.x;
    const int tid  = threadIdx.x;
    const int lane = tid & 31;
    const int warp = tid >> 5;

    if (tid < 2) {
        const int target = b + tid;
        int lo = 0, hi = M;
        while (lo < hi) {
            const int mid = (lo + hi) >> 1;
            if (batch[mid] < target) lo = mid + 1; else hi = mid;
        }
        bounds[tid] = lo;
    }
    __syncthreads();
    const int lo  = bounds[0];
    const int hi  = bounds[1];
    const int len = hi - lo;

    float m = -INFINITY;
    for (int i = tid; i < len; i += D) m = fmaxf(m, gate[lo + i]);
    #pragma unroll
    for (int o = 16; o; o >>= 1) m = fmaxf(m, __shfl_xor_sync(0xffffffffu, m, o));
    if (lane == 0) red[warp] = m;
    __syncthreads();
    m = fmaxf(fmaxf(red[0], red[1]), fmaxf(red[2], red[3]));
    __syncthreads();

    float s = 0.f;
    for (int i = tid; i < len; i += D) {
        const float e = expf(gate[lo + i] - m);
        if (i < EBUF_CAP) ebuf[i] = e;
        s += e;
    }
    #pragma unroll
    for (int o = 16; o; o >>= 1) s += __shfl_xor_sync(0xffffffffu, s, o);
    if (lane == 0) red[warp] = s;
    __syncthreads();
    const float denom = red[0] + red[1] + red[2] + red[3];
    const float inv = 1.f / (denom + 1e-16f);

    float acc = 0.f;
    const float b2c = b2[tid];
    for (int i = 0; i < len; i++) {
        const float w = (i < EBUF_CAP) ? ebuf[i] : expf(gate[lo + i] - m);
        acc = fmaf(w, T1[(size_t)(lo + i) * D + tid] + b2c, acc);
    }
    acc *= inv;
    __syncthreads();
    sacc[tid] = acc;
    __syncthreads();

    float u = l1b[tid];
    #pragma unroll 8
    for (int k = 0; k < D; k++) u = fmaf(sacc[k], l1W[k * D + tid], u);
    u = fmaxf(u, 0.f) * l2W[tid];
    #pragma unroll
    for (int o = 16; o; o >>= 1) u += __shfl_xor_sync(0xffffffffu, u, o);
    if (lane == 0) red[warp] = u;
    __syncthreads();
    if (tid == 0) out[b] = red[0] + red[1] + red[2] + red[3] + l2b[0];
}

// ---------------------------------------------------------------------------
// Pipeline uses linearity of GCN conv: scatter(x @ W) == gather(x) @ W.
//   g0 = gather(x)            -> t1
//   h1 = relu(g0@W1 + b1)     -> t0   (epilogue fused)
//   g1 = gather(h1)           -> t1
//   h2 = g1@W2                -> t0   (b2 fused downstream)
//   gate = relu((h2+b2)@gW1+gb1).gW2+gb2
//   out = attn(h2+b2, gate)
// ---------------------------------------------------------------------------
extern "C" void kernel_launch(void* const* d_in, const int* in_sizes, int n_in,
                              void* d_out, int out_size)
{
    const float* x     = (const float*)d_in[0];
    const int*   ei    = (const int*)  d_in[1];
    const float* ea    = (const float*)d_in[2];
    const int*   batch = (const int*)  d_in[3];
    const float* W1    = (const float*)d_in[4];
    const float* b1    = (const float*)d_in[5];
    const float* W2    = (const float*)d_in[6];
    const float* b2    = (const float*)d_in[7];
    const float* gW1   = (const float*)d_in[8];
    const float* gb1   = (const float*)d_in[9];
    const float* gW2   = (const float*)d_in[10];
    const float* gb2   = (const float*)d_in[11];
    const float* l1W   = (const float*)d_in[12];
    const float* l1b   = (const float*)d_in[13];
    const float* l2W   = (const float*)d_in[14];
    const float* l2b   = (const float*)d_in[15];
    float* out = (float*)d_out;

    const int M  = in_sizes[0] / D;
    const int NE = in_sizes[1] / 2;
    const int* src = ei;
    const int* dst = ei + NE;

    float *t0, *t1, *gate;
    int *rowptr, *cursor;
    int2 *edges;
    cudaGetSymbolAddress((void**)&t0,     g_t0);
    cudaGetSymbolAddress((void**)&t1,     g_t1);
    cudaGetSymbolAddress((void**)&gate,   g_gate);
    cudaGetSymbolAddress((void**)&rowptr, g_rowptr);
    cudaGetSymbolAddress((void**)&cursor, g_cursor);
    cudaGetSymbolAddress((void**)&edges,  g_edges);

    const size_t SMEM = (size_t)(D * D + ROWS_PER_BLK * D) * sizeof(float); // 96KB
    cudaFuncSetAttribute(gemm128_kernel, cudaFuncAttributeMaxDynamicSharedMemorySize, (int)SMEM);

    const int GB     = 296;                       // 2 blocks/SM for GEMM
    const int EBLK   = 2048;                      // edge-parallel kernels (grid-stride)
    const int GATB   = (M * 32 + 255) / 256;      // warp-per-node gather

    // ---- CSR build (once; reused by both aggregations) ----
    cudaMemsetAsync(cursor, 0, (size_t)M * sizeof(int), 0);
    deg_kernel       <<<EBLK, 256>>>(dst, cursor, NE);
    scan_fused_kernel<<<1, SF_THREADS>>>(cursor, rowptr, cursor, M);
    fill_kernel      <<<EBLK, 256>>>(src, dst, ea, cursor, edges, NE);
    // after fill: cursor[n] = row end

    // g0 = gather(x)
    gather_kernel<<<GATB, 256>>>(x, rowptr, cursor, edges, t1, M);
    // h1 = relu(g0 @ W1 + b1)
    gemm128_kernel<<<GB, 256, SMEM>>>(t1, W1, nullptr, b1, nullptr, nullptr,
                                      t0, nullptr, M, 0, 1);
    // g1 = gather(h1)
    gather_kernel<<<GATB, 256>>>(t0, rowptr, cursor, edges, t1, M);
    // h2 = g1 @ W2   (b2 fused downstream)
    gemm128_kernel<<<GB, 256, SMEM>>>(t1, W2, nullptr, nullptr, nullptr, nullptr,
                                      t0, nullptr, M, 0, 0);
    // gate = relu((h2+b2) @ gW1 + gb1) . gW2 + gb2
    gemm128_kernel<<<GB, 256, SMEM>>>(t0, gW1, b2, gb1, gW2, gb2,
                                      nullptr, gate, M, 2, 2);
    // per-graph softmax pool + final MLP
    attn_kernel<<<NGRAPH, 128>>>(t0, b2, gate, batch, l1W, l1b, l2W, l2b, out, M);
}